// round 3
// baseline (speedup 1.0000x reference)
#include <cuda_runtime.h>
#include <math_constants.h>

#define NC 64  // number of wells / columns

__global__ __launch_bounds__(256)
void energy_well_kernel(const float2* __restrict__ pos,
                        const float2* __restrict__ half_sz,
                        const float4* __restrict__ well_boxes,
                        const int4* __restrict__ avail,   // int32 per bool, row = 64 ints
                        const float* __restrict__ expo,
                        float* __restrict__ out,
                        int n)
{
    __shared__ float4 swb[NC];  // (xl, yl, xh, yh)
    if (threadIdx.x < NC) swb[threadIdx.x] = well_boxes[threadIdx.x];
    __syncthreads();

    int i = blockIdx.x * blockDim.x + threadIdx.x;
    if (i >= n) return;

    float2 p = pos[i];
    float2 h = half_sz[i];
    float xlo = p.x - h.x, xhi = p.x + h.x;
    float ylo = p.y - h.y, yhi = p.y + h.y;

    // Row of 64 int32 flags = 16x int4 vector loads (256B/thread, coalesced).
    const int4* arow = avail + (size_t)i * (NC / 4);

    float bestd = CUDART_INF_F;
    float bdx = 0.0f, bdy = 0.0f;

#pragma unroll
    for (int q = 0; q < NC / 4; q++) {
        int4 a = arow[q];
#pragma unroll
        for (int k = 0; k < 4; k++) {
            int c = q * 4 + k;
            int av = (k == 0) ? a.x : (k == 1) ? a.y : (k == 2) ? a.z : a.w;

            float4 wb = swb[c];
            float dx = fmaxf(fmaxf(wb.x - xlo, xhi - wb.z), 0.0f);
            float dy = fmaxf(fmaxf(wb.y - ylo, yhi - wb.w), 0.0f);
            float d = dx + dy;
            // argmin semantics: first index wins ties -> strict <
            if (av != 0 && d < bestd) {
                bestd = d;
                bdx = dx;
                bdy = dy;
            }
        }
    }

    float e = expo[i];
    out[i] = powf(bdx, e) + powf(bdy, e);
}

extern "C" void kernel_launch(void* const* d_in, const int* in_sizes, int n_in,
                              void* d_out, int out_size)
{
    // metadata order:
    // 0: inst_pos          (N,2) float32
    // 1: half_inst_sizes   (N,2) float32
    // 2: inst_areas        (N,)  float32   (unused by the reference output)
    // 3: well_boxes        (C,4) float32
    // 4: inst_cr_avail_map (N,C) bool -> serialized as int32
    // 5: exponents         (N,)  float32
    const float2* pos     = (const float2*)d_in[0];
    const float2* half_sz = (const float2*)d_in[1];
    const float4* wb      = (const float4*)d_in[3];
    const int4*  avail    = (const int4*)d_in[4];
    const float* expo     = (const float*)d_in[5];
    float* out = (float*)d_out;

    int n = out_size;  // N instances
    int threads = 256;
    int blocks = (n + threads - 1) / threads;
    energy_well_kernel<<<blocks, threads>>>(pos, half_sz, wb, avail, expo, out, n);
}

// round 4
// speedup vs baseline: 1.1663x; 1.1663x over previous
#include <cuda_runtime.h>
#include <math_constants.h>

#define NC 64          // wells / columns
#define BLOCK 128      // instances per block
#define ROW_CHUNKS (NC / 4)   // 16 int4 chunks per row

__global__ __launch_bounds__(BLOCK)
void energy_well_kernel(const float2* __restrict__ pos,
                        const float2* __restrict__ half_sz,
                        const float4* __restrict__ well_boxes,
                        const int4* __restrict__ avail,   // int32 per bool, row = 64 ints
                        const float* __restrict__ expo,
                        float* __restrict__ out,
                        int n)
{
    __shared__ float4 swb[NC];                    // (xl, yl, xh, yh)
    __shared__ int4 sav[BLOCK * ROW_CHUNKS];      // 32KB, XOR-swizzled rows

    int t = threadIdx.x;
    if (t < NC) swb[t] = well_boxes[t];

    int rowBase = blockIdx.x * BLOCK;
    int validRows = n - rowBase;
    if (validRows > BLOCK) validRows = BLOCK;
    int validChunks = validRows * ROW_CHUNKS;

    // ---- Stage avail rows into smem, fully coalesced global reads ----
    // chunk = global 16B chunk index within this block's slab.
    const int4* g = avail + (size_t)rowBase * ROW_CHUNKS;
#pragma unroll
    for (int k = 0; k < ROW_CHUNKS; k++) {
        int chunk = k * BLOCK + t;          // 0 .. BLOCK*16-1, lane-consecutive
        if (chunk < validChunks) {
            int r = chunk >> 4;             // row within block
            int q = chunk & 15;             // chunk within row
            // XOR swizzle: conflict-free STS.128 and LDS.128
            sav[r * ROW_CHUNKS + (q ^ (r & 15))] = g[chunk];
        }
    }
    __syncthreads();

    int i = rowBase + t;
    if (i >= n) return;

    float2 p = pos[i];
    float2 h = half_sz[i];
    float xlo = p.x - h.x, xhi = p.x + h.x;
    float ylo = p.y - h.y, yhi = p.y + h.y;

    float bestd = CUDART_INF_F;
    float bdx = 0.0f, bdy = 0.0f;

#pragma unroll
    for (int q = 0; q < ROW_CHUNKS; q++) {
        int4 a = sav[t * ROW_CHUNKS + (q ^ (t & 15))];
#pragma unroll
        for (int k = 0; k < 4; k++) {
            int c = q * 4 + k;
            int av = (k == 0) ? a.x : (k == 1) ? a.y : (k == 2) ? a.z : a.w;

            float4 wb = swb[c];
            float dx = fmaxf(fmaxf(wb.x - xlo, xhi - wb.z), 0.0f);
            float dy = fmaxf(fmaxf(wb.y - ylo, yhi - wb.w), 0.0f);
            float d = dx + dy;
            // argmin semantics: first index wins ties -> strict <
            if (av != 0 && d < bestd) {
                bestd = d;
                bdx = dx;
                bdy = dy;
            }
        }
    }

    float e = expo[i];
    float r;
    if (e == 2.0f) {
        r = bdx * bdx + bdy * bdy;          // dataset fast path (all exponents are 2)
    } else {
        r = powf(bdx, e) + powf(bdy, e);    // generic fallback
    }
    out[i] = r;
}

extern "C" void kernel_launch(void* const* d_in, const int* in_sizes, int n_in,
                              void* d_out, int out_size)
{
    // metadata order:
    // 0: inst_pos          (N,2) float32
    // 1: half_inst_sizes   (N,2) float32
    // 2: inst_areas        (N,)  float32   (unused by the reference output)
    // 3: well_boxes        (C,4) float32
    // 4: inst_cr_avail_map (N,C) bool -> serialized as int32
    // 5: exponents         (N,)  float32
    const float2* pos     = (const float2*)d_in[0];
    const float2* half_sz = (const float2*)d_in[1];
    const float4* wb      = (const float4*)d_in[3];
    const int4*  avail    = (const int4*)d_in[4];
    const float* expo     = (const float*)d_in[5];
    float* out = (float*)d_out;

    int n = out_size;  // N instances
    int blocks = (n + BLOCK - 1) / BLOCK;
    energy_well_kernel<<<blocks, BLOCK>>>(pos, half_sz, wb, avail, expo, out, n);
}